// round 10
// baseline (speedup 1.0000x reference)
#include <cuda_runtime.h>
#include <cuda_fp16.h>
#include <cstdint>

#define SEQ     2048
#define DIM     256
#define NHEAD   8
#define HD      32
#define NBATCH  4
#define NBH     (NBATCH * NHEAD)
#define QK_SCALE_L2E (0.17677669529663687f * 1.4426950408889634f)  // 32^-0.5 * log2(e)

// fp16 hi/lo split scratch
__device__ __align__(16) __half g_qh[NBH * SEQ * HD];
__device__ __align__(16) __half g_ql[NBH * SEQ * HD];
__device__ __align__(16) __half g_kh[NBH * SEQ * HD];
__device__ __align__(16) __half g_kl[NBH * SEQ * HD];
__device__ __align__(16) __half g_v16[NBH * SEQ * HD];   // V f16, [bh][n][d]
__device__ __align__(16) __half g_vth[NBH * HD * SEQ];   // V^T f16, [bh][d][n]
// pre-split GEMM operands
__device__ __align__(16) __half g_xh[8192 * 256];        // x hi, [m][k]
__device__ __align__(16) __half g_xl[8192 * 256];        // x lo
__device__ __align__(16) __half g_wh[768 * 256];         // W^T hi, [n][k]
__device__ __align__(16) __half g_wl[768 * 256];         // W^T lo

// ---------------------------------------------------------------------------
// helpers
// ---------------------------------------------------------------------------
__device__ __forceinline__ uint32_t pack_f16(float x0, float x1) {
    __half2 hh = __floats2half2_rn(x0, x1);
    return *reinterpret_cast<uint32_t*>(&hh);
}
__device__ __forceinline__ void split_pack_f16(float x0, float x1,
                                               uint32_t& h, uint32_t& l) {
    __half2 hh = __floats2half2_rn(x0, x1);
    float2 hf = __half22float2(hh);
    __half2 ll = __floats2half2_rn(x0 - hf.x, x1 - hf.y);
    h = *reinterpret_cast<uint32_t*>(&hh);
    l = *reinterpret_cast<uint32_t*>(&ll);
}
__device__ __forceinline__ float ex2(float x) {
    float y;
    asm("ex2.approx.f32 %0, %1;" : "=f"(y) : "f"(x));
    return y;
}

__device__ __forceinline__ void mma16816(float* c, const uint32_t* a,
                                         uint32_t b0, uint32_t b1) {
    asm volatile(
        "mma.sync.aligned.m16n8k16.row.col.f32.f16.f16.f32 "
        "{%0,%1,%2,%3}, {%4,%5,%6,%7}, {%8,%9}, {%0,%1,%2,%3};"
        : "+f"(c[0]), "+f"(c[1]), "+f"(c[2]), "+f"(c[3])
        : "r"(a[0]), "r"(a[1]), "r"(a[2]), "r"(a[3]), "r"(b0), "r"(b1));
}

__device__ __forceinline__ void ldm4(uint32_t* r, uint32_t saddr) {
    asm volatile("ldmatrix.sync.aligned.m8n8.x4.shared.b16 {%0,%1,%2,%3}, [%4];"
                 : "=r"(r[0]), "=r"(r[1]), "=r"(r[2]), "=r"(r[3]) : "r"(saddr));
}

__device__ __forceinline__ void cpa16(uint32_t s, const void* g) {
    uint64_t ga;
    asm("cvta.to.global.u64 %0, %1;" : "=l"(ga) : "l"(g));
    asm volatile("cp.async.cg.shared.global [%0], [%1], 16;" :: "r"(s), "l"(ga));
}
#define CP_COMMIT() asm volatile("cp.async.commit_group;" ::: "memory")
#define CP_WAIT(n)  asm volatile("cp.async.wait_group %0;" :: "n"(n) : "memory")

__device__ __forceinline__ uint32_t smem_u32(const void* p) {
    return (uint32_t)__cvta_generic_to_shared(p);
}

// ---------------------------------------------------------------------------
// Prep A: split x -> f16 hi/lo
// ---------------------------------------------------------------------------
__global__ __launch_bounds__(256) void xsplit(const float* __restrict__ x) {
    const size_t e0 = ((size_t)blockIdx.x * 256 + threadIdx.x) * 4;
    float4 v = *reinterpret_cast<const float4*>(&x[e0]);
    uint32_t h0, l0, h1, l1;
    split_pack_f16(v.x, v.y, h0, l0);
    split_pack_f16(v.z, v.w, h1, l1);
    *reinterpret_cast<uint2*>(&g_xh[e0]) = make_uint2(h0, h1);
    *reinterpret_cast<uint2*>(&g_xl[e0]) = make_uint2(l0, l1);
}

// ---------------------------------------------------------------------------
// Prep B: transpose + split W [k=256][n=768] -> W^T hi/lo [n][k]
// ---------------------------------------------------------------------------
__global__ __launch_bounds__(256) void wsplit(const float* __restrict__ W) {
    __shared__ float Ws[64][65];
    const int tid = threadIdx.x;
    const int n0 = blockIdx.x * 64;
    const int k0 = blockIdx.y * 64;

    const int kr = tid >> 2, nc = (tid & 3) << 4;
    #pragma unroll
    for (int j = 0; j < 4; j++) {
        float4 v = *reinterpret_cast<const float4*>(&W[(size_t)(k0 + kr) * 768 + n0 + nc + j * 4]);
        Ws[kr][nc + j * 4 + 0] = v.x; Ws[kr][nc + j * 4 + 1] = v.y;
        Ws[kr][nc + j * 4 + 2] = v.z; Ws[kr][nc + j * 4 + 3] = v.w;
    }
    __syncthreads();

    const int nr = tid >> 2, ks = (tid & 3) << 4;
    uint32_t hw[8], lw[8];
    #pragma unroll
    for (int j = 0; j < 8; j++)
        split_pack_f16(Ws[ks + 2 * j][nr], Ws[ks + 2 * j + 1][nr], hw[j], lw[j]);
    const size_t ob = (size_t)(n0 + nr) * 256 + k0 + ks;
    *reinterpret_cast<uint4*>(&g_wh[ob])     = make_uint4(hw[0], hw[1], hw[2], hw[3]);
    *reinterpret_cast<uint4*>(&g_wh[ob + 8]) = make_uint4(hw[4], hw[5], hw[6], hw[7]);
    *reinterpret_cast<uint4*>(&g_wl[ob])     = make_uint4(lw[0], lw[1], lw[2], lw[3]);
    *reinterpret_cast<uint4*>(&g_wl[ob + 8]) = make_uint4(lw[4], lw[5], lw[6], lw[7]);
}

// ---------------------------------------------------------------------------
// QKV GEMM via mma.sync f16 3-term (validated in R8).
// ---------------------------------------------------------------------------
#define ASTR 40
#define TILEB (128 * ASTR)   // f16 elems per buffer

__global__ __launch_bounds__(256) void qkv_mma(const float* __restrict__ bias) {
    extern __shared__ __half sm[];
    __half* sAh[2] = { sm,             sm + 4 * TILEB };
    __half* sAl[2] = { sm + 1 * TILEB, sm + 5 * TILEB };
    __half* sBh[2] = { sm + 2 * TILEB, sm + 6 * TILEB };
    __half* sBl[2] = { sm + 3 * TILEB, sm + 7 * TILEB };

    const int tid  = threadIdx.x;
    const int lane = tid & 31;
    const int wid  = tid >> 5;
    const int wm = wid & 1, wn = wid >> 1;
    const int m0 = blockIdx.x * 128;
    const int n0 = blockIdx.y * 128;

    const int crow = tid >> 1, cseg = (tid & 1) << 4;
    const uint32_t soff = (uint32_t)(crow * ASTR + cseg) * 2;

    auto load_stage = [&](int st, int kc) {
        const size_t ga = (size_t)(m0 + crow) * 256 + kc * 32 + cseg;
        const size_t gb = (size_t)(n0 + crow) * 256 + kc * 32 + cseg;
        uint32_t ah = smem_u32(sAh[st]) + soff;
        uint32_t al = smem_u32(sAl[st]) + soff;
        uint32_t bh = smem_u32(sBh[st]) + soff;
        uint32_t bl = smem_u32(sBl[st]) + soff;
        cpa16(ah, g_xh + ga); cpa16(ah + 16, g_xh + ga + 8);
        cpa16(al, g_xl + ga); cpa16(al + 16, g_xl + ga + 8);
        cpa16(bh, g_wh + gb); cpa16(bh + 16, g_wh + gb + 8);
        cpa16(bl, g_wl + gb); cpa16(bl + 16, g_wl + gb + 8);
    };

    float c[4][4][4];
    #pragma unroll
    for (int mi = 0; mi < 4; mi++)
        #pragma unroll
        for (int j = 0; j < 4; j++)
            { c[mi][j][0] = c[mi][j][1] = c[mi][j][2] = c[mi][j][3] = 0.f; }

    const int a_r = (lane & 7) + ((lane >> 3) & 1) * 8;
    const int a_c = (lane >> 4) * 8;
    const int b_r = lane & 7;
    const int b_c = (lane >> 3) * 8;

    load_stage(0, 0);
    CP_COMMIT();

    for (int kc = 0; kc < 8; kc++) {
        if (kc + 1 < 8) { load_stage((kc + 1) & 1, kc + 1); CP_COMMIT(); CP_WAIT(1); }
        else            { CP_WAIT(0); }
        __syncthreads();
        const int st = kc & 1;

        uint32_t bh[4][4], bl[4][4];
        const uint32_t bbase_h = smem_u32(sBh[st]);
        const uint32_t bbase_l = smem_u32(sBl[st]);
        #pragma unroll
        for (int j = 0; j < 4; j++) {
            const uint32_t off = (uint32_t)((wn * 32 + j * 8 + b_r) * ASTR + b_c) * 2;
            ldm4(bh[j], bbase_h + off);
            ldm4(bl[j], bbase_l + off);
        }

        const uint32_t abase_h = smem_u32(sAh[st]);
        const uint32_t abase_l = smem_u32(sAl[st]);
        #pragma unroll
        for (int mi = 0; mi < 4; mi++) {
            uint32_t ah[2][4], al[2][4];
            #pragma unroll
            for (int kk = 0; kk < 2; kk++) {
                const uint32_t off =
                    (uint32_t)((wm * 64 + mi * 16 + a_r) * ASTR + kk * 16 + a_c) * 2;
                ldm4(ah[kk], abase_h + off);
                ldm4(al[kk], abase_l + off);
            }
            #pragma unroll
            for (int j = 0; j < 4; j++) {
                mma16816(c[mi][j], ah[0], bh[j][0], bh[j][1]);
                mma16816(c[mi][j], ah[1], bh[j][2], bh[j][3]);
                mma16816(c[mi][j], ah[0], bl[j][0], bl[j][1]);
                mma16816(c[mi][j], ah[1], bl[j][2], bl[j][3]);
                mma16816(c[mi][j], al[0], bh[j][0], bh[j][1]);
                mma16816(c[mi][j], al[1], bh[j][2], bh[j][3]);
            }
        }
        __syncthreads();
    }

    // ---- epilogue ----
    const int which = n0 >> 8;            // 0=Q 1=K 2=V
    const int r4 = lane >> 2, t4 = lane & 3;
    #pragma unroll
    for (int j = 0; j < 4; j++) {
        const int n3 = n0 + wn * 32 + j * 8 + t4 * 2;
        const int cc = n3 & 255, h = cc >> 5, d = cc & 31;
        const float b0 = __ldg(&bias[n3]), b1 = __ldg(&bias[n3 + 1]);
        #pragma unroll
        for (int mi = 0; mi < 4; mi++) {
            #pragma unroll
            for (int half = 0; half < 2; half++) {
                const int m = m0 + wm * 64 + mi * 16 + r4 + half * 8;
                const int bb = m >> 11, n = m & 2047;
                float v0 = c[mi][j][2 * half + 0] + b0;
                float v1 = c[mi][j][2 * half + 1] + b1;
                const size_t idx = ((size_t)(bb * NHEAD + h) * SEQ + n) * HD + d;
                if (which == 0) {
                    v0 *= QK_SCALE_L2E; v1 *= QK_SCALE_L2E;
                    uint32_t hw, lw;
                    split_pack_f16(v0, v1, hw, lw);
                    *reinterpret_cast<uint32_t*>(&g_qh[idx]) = hw;
                    *reinterpret_cast<uint32_t*>(&g_ql[idx]) = lw;
                } else if (which == 1) {
                    uint32_t hw, lw;
                    split_pack_f16(v0, v1, hw, lw);
                    *reinterpret_cast<uint32_t*>(&g_kh[idx]) = hw;
                    *reinterpret_cast<uint32_t*>(&g_kl[idx]) = lw;
                } else {
                    *reinterpret_cast<uint32_t*>(&g_v16[idx]) = pack_f16(v0, v1);
                }
            }
        }
    }
}

// ---------------------------------------------------------------------------
// V transpose (f16): g_v16[bh][n][d] -> g_vth[bh][d][n]
// ---------------------------------------------------------------------------
__global__ __launch_bounds__(256) void vtrans() {
    __shared__ uint32_t Vs[128][17];
    const int tid = threadIdx.x;
    const int bh = blockIdx.y;
    const int n0 = blockIdx.x * 128;
    const uint32_t* gv = reinterpret_cast<const uint32_t*>(g_v16) +
                         ((size_t)bh * SEQ + n0) * (HD / 2);

    const int r = tid >> 1, c0 = (tid & 1) * 8;
    uint4 a = *reinterpret_cast<const uint4*>(gv + (size_t)r * 16 + c0);
    uint4 b = *reinterpret_cast<const uint4*>(gv + (size_t)r * 16 + c0 + 4);
    Vs[r][c0 + 0] = a.x; Vs[r][c0 + 1] = a.y; Vs[r][c0 + 2] = a.z; Vs[r][c0 + 3] = a.w;
    Vs[r][c0 + 4] = b.x; Vs[r][c0 + 5] = b.y; Vs[r][c0 + 6] = b.z; Vs[r][c0 + 7] = b.w;
    __syncthreads();

    const int dp = tid & 15, nblk = tid >> 4;
    uint32_t lo[4], hi[4];
    #pragma unroll
    for (int j = 0; j < 4; j++) {
        uint32_t w0 = Vs[nblk * 8 + 2 * j][dp];
        uint32_t w1 = Vs[nblk * 8 + 2 * j + 1][dp];
        lo[j] = __byte_perm(w0, w1, 0x5410);
        hi[j] = __byte_perm(w0, w1, 0x7632);
    }
    uint32_t* gt = reinterpret_cast<uint32_t*>(g_vth);
    const size_t o_lo = (((size_t)bh * HD + 2 * dp) * SEQ + n0 + nblk * 8) >> 1;
    const size_t o_hi = (((size_t)bh * HD + 2 * dp + 1) * SEQ + n0 + nblk * 8) >> 1;
    *reinterpret_cast<uint4*>(gt + o_lo) = make_uint4(lo[0], lo[1], lo[2], lo[3]);
    *reinterpret_cast<uint4*>(gt + o_hi) = make_uint4(hi[0], hi[1], hi[2], hi[3]);
}

// ---------------------------------------------------------------------------
// Flash attention: q-tile 128 rows (8 warps x 16 rows), k-tile 64.
// QK 3-term f16, PV single-term, exp2 softmax (log2e folded into Q).
// ---------------------------------------------------------------------------
#define KSTR 40
#define VSTR 72

__global__ __launch_bounds__(256) void flash_attn(float* __restrict__ out) {
    __shared__ __half sKh[2][64 * KSTR];
    __shared__ __half sKl[2][64 * KSTR];
    __shared__ __half sVh[2][32 * VSTR];

    const int tid  = threadIdx.x;
    const int lane = tid & 31;
    const int wid  = tid >> 5;
    const int bx   = blockIdx.x;
    const int qt   = (bx < 8) ? (15 - bx) : (bx - 8);   // heavy (bottom) tiles first
    const int bh   = blockIdx.y;
    const int b    = bh >> 3, h = bh & 7;

    const uint32_t aKh[2] = { smem_u32(sKh[0]), smem_u32(sKh[1]) };
    const uint32_t aKl[2] = { smem_u32(sKl[0]), smem_u32(sKl[1]) };
    const uint32_t aVh[2] = { smem_u32(sVh[0]), smem_u32(sVh[1]) };

    // ---- Q fragments (warp owns rows qt*128 + wid*16 .. +15) ----
    uint32_t qh[2][4], ql[2][4];
    {
        const size_t qbase = ((size_t)bh * SEQ + qt * 128 + wid * 16) * HD;
        const uint32_t* qhp = reinterpret_cast<const uint32_t*>(g_qh) + qbase / 2;
        const uint32_t* qlp = reinterpret_cast<const uint32_t*>(g_ql) + qbase / 2;
        const int r = lane >> 2, t4 = lane & 3;
        #pragma unroll
        for (int kk = 0; kk < 2; kk++) {
            qh[kk][0] = qhp[r * 16 + kk * 8 + t4];
            qh[kk][1] = qhp[(r + 8) * 16 + kk * 8 + t4];
            qh[kk][2] = qhp[r * 16 + kk * 8 + 4 + t4];
            qh[kk][3] = qhp[(r + 8) * 16 + kk * 8 + 4 + t4];
            ql[kk][0] = qlp[r * 16 + kk * 8 + t4];
            ql[kk][1] = qlp[(r + 8) * 16 + kk * 8 + t4];
            ql[kk][2] = qlp[r * 16 + kk * 8 + 4 + t4];
            ql[kk][3] = qlp[(r + 8) * 16 + kk * 8 + 4 + t4];
        }
    }

    // top (rows < 1024): 16 k-tiles; bottom: causal, 2*qt+2 k-tiles
    const int nkt = (qt < 8) ? 16 : (2 * qt + 2);
    float o[4][4] = {};
    float l0 = 0.f, l1 = 0.f;

    // 256-thread tile loader: 3 cp.async per thread
    auto load_tiles = [&](int st, int kt) {
        {   // K hi/lo: 64 rows x 64B -> 256 chunks of 16B
            const int row = tid >> 2, seg = (tid & 3) << 3;
            const size_t gk = ((size_t)bh * SEQ + kt * 64 + row) * HD + seg;
            const uint32_t sk = (uint32_t)(row * KSTR + seg) * 2;
            cpa16(aKh[st] + sk, g_kh + gk);
            cpa16(aKl[st] + sk, g_kl + gk);
        }
        {   // VT: 32 rows x 128B -> 256 chunks of 16B
            const int dr = tid >> 3, seg = (tid & 7) << 3;
            const size_t gv = ((size_t)bh * HD + dr) * SEQ + kt * 64 + seg;
            const uint32_t sv = (uint32_t)(dr * VSTR + seg) * 2;
            cpa16(aVh[st] + sv, g_vth + gv);
        }
    };

    load_tiles(0, 0);
    CP_COMMIT();

    const int r4 = lane >> 2, t4 = lane & 3;
    const int lm_row = lane & 7, lm_cb = lane >> 3;
    const int wr0 = qt * 128 + wid * 16;   // warp's first q row

    for (int kt = 0; kt < nkt; kt++) {
        if (kt + 1 < nkt) { load_tiles((kt + 1) & 1, kt + 1); CP_COMMIT(); CP_WAIT(1); }
        else              { CP_WAIT(0); }
        __syncthreads();

        const int st = kt & 1;

        // ---- S = Q K^T (3-term f16) ----
        float s[8][4];
        #pragma unroll
        for (int j = 0; j < 8; j++) { s[j][0] = s[j][1] = s[j][2] = s[j][3] = 0.f; }

        #pragma unroll
        for (int j = 0; j < 8; j++) {
            uint32_t kh[4], kl[4];
            const uint32_t off = (uint32_t)((j * 8 + lm_row) * KSTR + lm_cb * 8) * 2;
            ldm4(kh, aKh[st] + off);
            ldm4(kl, aKl[st] + off);
            mma16816(s[j], qh[0], kh[0], kh[1]);
            mma16816(s[j], qh[1], kh[2], kh[3]);
            mma16816(s[j], qh[0], kl[0], kl[1]);
            mma16816(s[j], qh[1], kl[2], kl[3]);
            mma16816(s[j], ql[0], kh[0], kh[1]);
            mma16816(s[j], ql[1], kh[2], kh[3]);
        }

        // ---- p = 2^s, causal mask where the tile can cross the diagonal ----
        const bool diag = (qt >= 8) && ((kt + 1) * 64 > wr0);
        #pragma unroll
        for (int j = 0; j < 8; j++) {
            float p0 = ex2(s[j][0]), p1 = ex2(s[j][1]);
            float p2 = ex2(s[j][2]), p3 = ex2(s[j][3]);
            if (diag) {
                const int key0 = kt * 64 + j * 8 + t4 * 2;
                const int r0 = wr0 + r4;
                if (key0     > r0)     p0 = 0.f;
                if (key0 + 1 > r0)     p1 = 0.f;
                if (key0     > r0 + 8) p2 = 0.f;
                if (key0 + 1 > r0 + 8) p3 = 0.f;
            }
            l0 += p0 + p1; l1 += p2 + p3;
            s[j][0] = p0; s[j][1] = p1; s[j][2] = p2; s[j][3] = p3;
        }

        // ---- P -> f16 A frags (single term) ----
        uint32_t ah[4][4];
        #pragma unroll
        for (int kk = 0; kk < 4; kk++) {
            const int j0 = 2 * kk, j1 = 2 * kk + 1;
            ah[kk][0] = pack_f16(s[j0][0], s[j0][1]);
            ah[kk][1] = pack_f16(s[j0][2], s[j0][3]);
            ah[kk][2] = pack_f16(s[j1][0], s[j1][1]);
            ah[kk][3] = pack_f16(s[j1][2], s[j1][3]);
        }

        // ---- O += P V (single term) ----
        #pragma unroll
        for (int nd = 0; nd < 4; nd++) {
            uint32_t vh[8];
            const uint32_t ro = (uint32_t)((nd * 8 + lm_row) * VSTR) * 2;
            ldm4(vh,     aVh[st] + ro + (uint32_t)(lm_cb * 8) * 2);
            ldm4(vh + 4, aVh[st] + ro + (uint32_t)(32 + lm_cb * 8) * 2);
            #pragma unroll
            for (int kk = 0; kk < 4; kk++)
                mma16816(o[nd], ah[kk], vh[2 * kk], vh[2 * kk + 1]);
        }
        __syncthreads();
    }

    l0 += __shfl_xor_sync(0xffffffffu, l0, 1);
    l0 += __shfl_xor_sync(0xffffffffu, l0, 2);
    l1 += __shfl_xor_sync(0xffffffffu, l1, 1);
    l1 += __shfl_xor_sync(0xffffffffu, l1, 2);
    const float inv0 = 1.f / l0, inv1 = 1.f / l1;

    const int row0 = wr0 + r4;
    #pragma unroll
    for (int nd = 0; nd < 4; nd++) {
        const int d0 = nd * 8 + t4 * 2;
        const size_t o0 = ((size_t)(b * SEQ + row0)) * DIM + h * HD + d0;
        const size_t o1 = ((size_t)(b * SEQ + row0 + 8)) * DIM + h * HD + d0;
        *reinterpret_cast<float2*>(&out[o0]) = make_float2(o[nd][0] * inv0, o[nd][1] * inv0);
        *reinterpret_cast<float2*>(&out[o1]) = make_float2(o[nd][2] * inv1, o[nd][3] * inv1);
    }
}

extern "C" void kernel_launch(void* const* d_in, const int* in_sizes, int n_in,
                              void* d_out, int out_size) {
    const float* x    = (const float*)d_in[0];
    const float* W    = (const float*)d_in[1];
    const float* bias = (const float*)d_in[2];
    float* out = (float*)d_out;

    static int init_done = 0;
    if (!init_done) {
        cudaFuncSetAttribute(qkv_mma,
                             cudaFuncAttributeMaxDynamicSharedMemorySize,
                             8 * TILEB * (int)sizeof(__half));
        init_done = 1;
    }

    xsplit<<<2048, 256>>>(x);
    wsplit<<<dim3(12, 4), 256>>>(W);
    qkv_mma<<<dim3(64, 6), 256, 8 * TILEB * sizeof(__half)>>>(bias);

    dim3 vt_grid(16, 32);
    vtrans<<<vt_grid, 256>>>();

    dim3 attn_grid(16, 32);
    flash_attn<<<attn_grid, 256>>>(out);
}

// round 12
// speedup vs baseline: 1.3730x; 1.3730x over previous
#include <cuda_runtime.h>
#include <cuda_fp16.h>
#include <cstdint>

#define SEQ     2048
#define DIM     256
#define NHEAD   8
#define HD      32
#define NBATCH  4
#define NBH     (NBATCH * NHEAD)
#define QK_SCALE_L2E (0.17677669529663687f * 1.4426950408889634f)  // 32^-0.5 * log2(e)

// f16 attention operands
__device__ __align__(16) __half g_q16[NBH * SEQ * HD];   // Q f16 (pre-scaled), [bh][n][d]
__device__ __align__(16) __half g_k16[NBH * SEQ * HD];   // K f16, [bh][n][d]
__device__ __align__(16) __half g_v16[NBH * SEQ * HD];   // V f16, [bh][n][d]
__device__ __align__(16) __half g_vth[NBH * HD * SEQ];   // V^T f16, [bh][d][n]
// pre-split GEMM operands (GEMM stays 3-term for accuracy)
__device__ __align__(16) __half g_xh[8192 * 256];        // x hi, [m][k]
__device__ __align__(16) __half g_xl[8192 * 256];        // x lo
__device__ __align__(16) __half g_wh[768 * 256];         // W^T hi, [n][k]
__device__ __align__(16) __half g_wl[768 * 256];         // W^T lo

// ---------------------------------------------------------------------------
// helpers
// ---------------------------------------------------------------------------
__device__ __forceinline__ uint32_t pack_f16(float x0, float x1) {
    __half2 hh = __floats2half2_rn(x0, x1);
    return *reinterpret_cast<uint32_t*>(&hh);
}
__device__ __forceinline__ void split_pack_f16(float x0, float x1,
                                               uint32_t& h, uint32_t& l) {
    __half2 hh = __floats2half2_rn(x0, x1);
    float2 hf = __half22float2(hh);
    __half2 ll = __floats2half2_rn(x0 - hf.x, x1 - hf.y);
    h = *reinterpret_cast<uint32_t*>(&hh);
    l = *reinterpret_cast<uint32_t*>(&ll);
}
__device__ __forceinline__ float ex2(float x) {
    float y;
    asm("ex2.approx.f32 %0, %1;" : "=f"(y) : "f"(x));
    return y;
}

__device__ __forceinline__ void mma16816(float* c, const uint32_t* a,
                                         uint32_t b0, uint32_t b1) {
    asm volatile(
        "mma.sync.aligned.m16n8k16.row.col.f32.f16.f16.f32 "
        "{%0,%1,%2,%3}, {%4,%5,%6,%7}, {%8,%9}, {%0,%1,%2,%3};"
        : "+f"(c[0]), "+f"(c[1]), "+f"(c[2]), "+f"(c[3])
        : "r"(a[0]), "r"(a[1]), "r"(a[2]), "r"(a[3]), "r"(b0), "r"(b1));
}

__device__ __forceinline__ void ldm4(uint32_t* r, uint32_t saddr) {
    asm volatile("ldmatrix.sync.aligned.m8n8.x4.shared.b16 {%0,%1,%2,%3}, [%4];"
                 : "=r"(r[0]), "=r"(r[1]), "=r"(r[2]), "=r"(r[3]) : "r"(saddr));
}

__device__ __forceinline__ void cpa16(uint32_t s, const void* g) {
    uint64_t ga;
    asm("cvta.to.global.u64 %0, %1;" : "=l"(ga) : "l"(g));
    asm volatile("cp.async.cg.shared.global [%0], [%1], 16;" :: "r"(s), "l"(ga));
}
#define CP_COMMIT() asm volatile("cp.async.commit_group;" ::: "memory")
#define CP_WAIT(n)  asm volatile("cp.async.wait_group %0;" :: "n"(n) : "memory")

__device__ __forceinline__ uint32_t smem_u32(const void* p) {
    return (uint32_t)__cvta_generic_to_shared(p);
}

// ---------------------------------------------------------------------------
// Prep A: split x -> f16 hi/lo
// ---------------------------------------------------------------------------
__global__ __launch_bounds__(256) void xsplit(const float* __restrict__ x) {
    const size_t e0 = ((size_t)blockIdx.x * 256 + threadIdx.x) * 4;
    float4 v = *reinterpret_cast<const float4*>(&x[e0]);
    uint32_t h0, l0, h1, l1;
    split_pack_f16(v.x, v.y, h0, l0);
    split_pack_f16(v.z, v.w, h1, l1);
    *reinterpret_cast<uint2*>(&g_xh[e0]) = make_uint2(h0, h1);
    *reinterpret_cast<uint2*>(&g_xl[e0]) = make_uint2(l0, l1);
}

// ---------------------------------------------------------------------------
// Prep B: transpose + split W [k=256][n=768] -> W^T hi/lo [n][k]
// ---------------------------------------------------------------------------
__global__ __launch_bounds__(256) void wsplit(const float* __restrict__ W) {
    __shared__ float Ws[64][65];
    const int tid = threadIdx.x;
    const int n0 = blockIdx.x * 64;
    const int k0 = blockIdx.y * 64;

    const int kr = tid >> 2, nc = (tid & 3) << 4;
    #pragma unroll
    for (int j = 0; j < 4; j++) {
        float4 v = *reinterpret_cast<const float4*>(&W[(size_t)(k0 + kr) * 768 + n0 + nc + j * 4]);
        Ws[kr][nc + j * 4 + 0] = v.x; Ws[kr][nc + j * 4 + 1] = v.y;
        Ws[kr][nc + j * 4 + 2] = v.z; Ws[kr][nc + j * 4 + 3] = v.w;
    }
    __syncthreads();

    const int nr = tid >> 2, ks = (tid & 3) << 4;
    uint32_t hw[8], lw[8];
    #pragma unroll
    for (int j = 0; j < 8; j++)
        split_pack_f16(Ws[ks + 2 * j][nr], Ws[ks + 2 * j + 1][nr], hw[j], lw[j]);
    const size_t ob = (size_t)(n0 + nr) * 256 + k0 + ks;
    *reinterpret_cast<uint4*>(&g_wh[ob])     = make_uint4(hw[0], hw[1], hw[2], hw[3]);
    *reinterpret_cast<uint4*>(&g_wh[ob + 8]) = make_uint4(hw[4], hw[5], hw[6], hw[7]);
    *reinterpret_cast<uint4*>(&g_wl[ob])     = make_uint4(lw[0], lw[1], lw[2], lw[3]);
    *reinterpret_cast<uint4*>(&g_wl[ob + 8]) = make_uint4(lw[4], lw[5], lw[6], lw[7]);
}

// ---------------------------------------------------------------------------
// QKV GEMM via mma.sync f16 3-term (validated).  Epilogue now stores plain
// f16 Q (scaled incl log2e), K, V.
// ---------------------------------------------------------------------------
#define ASTR 40
#define TILEB (128 * ASTR)   // f16 elems per buffer

__global__ __launch_bounds__(256) void qkv_mma(const float* __restrict__ bias) {
    extern __shared__ __half sm[];
    __half* sAh[2] = { sm,             sm + 4 * TILEB };
    __half* sAl[2] = { sm + 1 * TILEB, sm + 5 * TILEB };
    __half* sBh[2] = { sm + 2 * TILEB, sm + 6 * TILEB };
    __half* sBl[2] = { sm + 3 * TILEB, sm + 7 * TILEB };

    const int tid  = threadIdx.x;
    const int lane = tid & 31;
    const int wid  = tid >> 5;
    const int wm = wid & 1, wn = wid >> 1;
    const int m0 = blockIdx.x * 128;
    const int n0 = blockIdx.y * 128;

    const int crow = tid >> 1, cseg = (tid & 1) << 4;
    const uint32_t soff = (uint32_t)(crow * ASTR + cseg) * 2;

    auto load_stage = [&](int st, int kc) {
        const size_t ga = (size_t)(m0 + crow) * 256 + kc * 32 + cseg;
        const size_t gb = (size_t)(n0 + crow) * 256 + kc * 32 + cseg;
        uint32_t ah = smem_u32(sAh[st]) + soff;
        uint32_t al = smem_u32(sAl[st]) + soff;
        uint32_t bh = smem_u32(sBh[st]) + soff;
        uint32_t bl = smem_u32(sBl[st]) + soff;
        cpa16(ah, g_xh + ga); cpa16(ah + 16, g_xh + ga + 8);
        cpa16(al, g_xl + ga); cpa16(al + 16, g_xl + ga + 8);
        cpa16(bh, g_wh + gb); cpa16(bh + 16, g_wh + gb + 8);
        cpa16(bl, g_wl + gb); cpa16(bl + 16, g_wl + gb + 8);
    };

    float c[4][4][4];
    #pragma unroll
    for (int mi = 0; mi < 4; mi++)
        #pragma unroll
        for (int j = 0; j < 4; j++)
            { c[mi][j][0] = c[mi][j][1] = c[mi][j][2] = c[mi][j][3] = 0.f; }

    const int a_r = (lane & 7) + ((lane >> 3) & 1) * 8;
    const int a_c = (lane >> 4) * 8;
    const int b_r = lane & 7;
    const int b_c = (lane >> 3) * 8;

    load_stage(0, 0);
    CP_COMMIT();

    for (int kc = 0; kc < 8; kc++) {
        if (kc + 1 < 8) { load_stage((kc + 1) & 1, kc + 1); CP_COMMIT(); CP_WAIT(1); }
        else            { CP_WAIT(0); }
        __syncthreads();
        const int st = kc & 1;

        uint32_t bh[4][4], bl[4][4];
        const uint32_t bbase_h = smem_u32(sBh[st]);
        const uint32_t bbase_l = smem_u32(sBl[st]);
        #pragma unroll
        for (int j = 0; j < 4; j++) {
            const uint32_t off = (uint32_t)((wn * 32 + j * 8 + b_r) * ASTR + b_c) * 2;
            ldm4(bh[j], bbase_h + off);
            ldm4(bl[j], bbase_l + off);
        }

        const uint32_t abase_h = smem_u32(sAh[st]);
        const uint32_t abase_l = smem_u32(sAl[st]);
        #pragma unroll
        for (int mi = 0; mi < 4; mi++) {
            uint32_t ah[2][4], al[2][4];
            #pragma unroll
            for (int kk = 0; kk < 2; kk++) {
                const uint32_t off =
                    (uint32_t)((wm * 64 + mi * 16 + a_r) * ASTR + kk * 16 + a_c) * 2;
                ldm4(ah[kk], abase_h + off);
                ldm4(al[kk], abase_l + off);
            }
            #pragma unroll
            for (int j = 0; j < 4; j++) {
                mma16816(c[mi][j], ah[0], bh[j][0], bh[j][1]);
                mma16816(c[mi][j], ah[1], bh[j][2], bh[j][3]);
                mma16816(c[mi][j], ah[0], bl[j][0], bl[j][1]);
                mma16816(c[mi][j], ah[1], bl[j][2], bl[j][3]);
                mma16816(c[mi][j], al[0], bh[j][0], bh[j][1]);
                mma16816(c[mi][j], al[1], bh[j][2], bh[j][3]);
            }
        }
        __syncthreads();
    }

    // ---- epilogue: plain f16 Q/K/V ----
    const int which = n0 >> 8;            // 0=Q 1=K 2=V
    const int r4 = lane >> 2, t4 = lane & 3;
    #pragma unroll
    for (int j = 0; j < 4; j++) {
        const int n3 = n0 + wn * 32 + j * 8 + t4 * 2;
        const int cc = n3 & 255, h = cc >> 5, d = cc & 31;
        const float b0 = __ldg(&bias[n3]), b1 = __ldg(&bias[n3 + 1]);
        #pragma unroll
        for (int mi = 0; mi < 4; mi++) {
            #pragma unroll
            for (int half = 0; half < 2; half++) {
                const int m = m0 + wm * 64 + mi * 16 + r4 + half * 8;
                const int bb = m >> 11, n = m & 2047;
                float v0 = c[mi][j][2 * half + 0] + b0;
                float v1 = c[mi][j][2 * half + 1] + b1;
                const size_t idx = ((size_t)(bb * NHEAD + h) * SEQ + n) * HD + d;
                if (which == 0) {
                    *reinterpret_cast<uint32_t*>(&g_q16[idx]) =
                        pack_f16(v0 * QK_SCALE_L2E, v1 * QK_SCALE_L2E);
                } else if (which == 1) {
                    *reinterpret_cast<uint32_t*>(&g_k16[idx]) = pack_f16(v0, v1);
                } else {
                    *reinterpret_cast<uint32_t*>(&g_v16[idx]) = pack_f16(v0, v1);
                }
            }
        }
    }
}

// ---------------------------------------------------------------------------
// V transpose (f16): g_v16[bh][n][d] -> g_vth[bh][d][n]
// ---------------------------------------------------------------------------
__global__ __launch_bounds__(256) void vtrans() {
    __shared__ uint32_t Vs[128][17];
    const int tid = threadIdx.x;
    const int bh = blockIdx.y;
    const int n0 = blockIdx.x * 128;
    const uint32_t* gv = reinterpret_cast<const uint32_t*>(g_v16) +
                         ((size_t)bh * SEQ + n0) * (HD / 2);

    const int r = tid >> 1, c0 = (tid & 1) * 8;
    uint4 a = *reinterpret_cast<const uint4*>(gv + (size_t)r * 16 + c0);
    uint4 b = *reinterpret_cast<const uint4*>(gv + (size_t)r * 16 + c0 + 4);
    Vs[r][c0 + 0] = a.x; Vs[r][c0 + 1] = a.y; Vs[r][c0 + 2] = a.z; Vs[r][c0 + 3] = a.w;
    Vs[r][c0 + 4] = b.x; Vs[r][c0 + 5] = b.y; Vs[r][c0 + 6] = b.z; Vs[r][c0 + 7] = b.w;
    __syncthreads();

    const int dp = tid & 15, nblk = tid >> 4;
    uint32_t lo[4], hi[4];
    #pragma unroll
    for (int j = 0; j < 4; j++) {
        uint32_t w0 = Vs[nblk * 8 + 2 * j][dp];
        uint32_t w1 = Vs[nblk * 8 + 2 * j + 1][dp];
        lo[j] = __byte_perm(w0, w1, 0x5410);
        hi[j] = __byte_perm(w0, w1, 0x7632);
    }
    uint32_t* gt = reinterpret_cast<uint32_t*>(g_vth);
    const size_t o_lo = (((size_t)bh * HD + 2 * dp) * SEQ + n0 + nblk * 8) >> 1;
    const size_t o_hi = (((size_t)bh * HD + 2 * dp + 1) * SEQ + n0 + nblk * 8) >> 1;
    *reinterpret_cast<uint4*>(gt + o_lo) = make_uint4(lo[0], lo[1], lo[2], lo[3]);
    *reinterpret_cast<uint4*>(gt + o_hi) = make_uint4(hi[0], hi[1], hi[2], hi[3]);
}

// ---------------------------------------------------------------------------
// Flash attention (R8 shape: 64-row q-tile, 4 warps, 1024 CTAs), plain f16:
// QK single-term, PV single-term, exp2 softmax (log2e folded into Q).
// ---------------------------------------------------------------------------
#define KSTR 40
#define VSTR 72

__global__ __launch_bounds__(128) void flash_attn(float* __restrict__ out) {
    __shared__ __half sK [2][64 * KSTR];
    __shared__ __half sVh[2][32 * VSTR];

    const int tid  = threadIdx.x;
    const int lane = tid & 31;
    const int wid  = tid >> 5;
    const int qt   = 31 - blockIdx.x;     // heavy (long causal) tiles first
    const int bh   = blockIdx.y;
    const int b    = bh >> 3, h = bh & 7;

    const uint32_t aK [2] = { smem_u32(sK[0]),  smem_u32(sK[1])  };
    const uint32_t aVh[2] = { smem_u32(sVh[0]), smem_u32(sVh[1]) };

    // ---- Q fragments ----
    uint32_t qh[2][4];
    {
        const size_t qbase = ((size_t)bh * SEQ + qt * 64 + wid * 16) * HD;
        const uint32_t* qhp = reinterpret_cast<const uint32_t*>(g_q16) + qbase / 2;
        const int r = lane >> 2, t4 = lane & 3;
        #pragma unroll
        for (int kk = 0; kk < 2; kk++) {
            qh[kk][0] = qhp[r * 16 + kk * 8 + t4];
            qh[kk][1] = qhp[(r + 8) * 16 + kk * 8 + t4];
            qh[kk][2] = qhp[r * 16 + kk * 8 + 4 + t4];
            qh[kk][3] = qhp[(r + 8) * 16 + kk * 8 + 4 + t4];
        }
    }

    const int nkt = (qt < 16) ? 16 : (qt + 1);
    float o[4][4] = {};
    float l0 = 0.f, l1 = 0.f;

    auto load_tiles = [&](int st, int kt) {
        {   // K: 64 rows x 64B; 128 thr x 32B
            const int row = tid >> 1, seg = (tid & 1) << 4;
            const size_t gk = ((size_t)bh * SEQ + kt * 64 + row) * HD + seg;
            const uint32_t sk = (uint32_t)(row * KSTR + seg) * 2;
            cpa16(aK[st] + sk,      g_k16 + gk);
            cpa16(aK[st] + sk + 16, g_k16 + gk + 8);
        }
        {   // VT: 32 rows x 128B; 128 thr x 32B
            const int dr = tid >> 2, seg = (tid & 3) << 4;
            const size_t gv = ((size_t)bh * HD + dr) * SEQ + kt * 64 + seg;
            const uint32_t sv = (uint32_t)(dr * VSTR + seg) * 2;
            cpa16(aVh[st] + sv,      g_vth + gv);
            cpa16(aVh[st] + sv + 16, g_vth + gv + 8);
        }
    };

    load_tiles(0, 0);
    CP_COMMIT();

    const int r4 = lane >> 2, t4 = lane & 3;
    const int lm_row = lane & 7, lm_cb = lane >> 3;

    for (int kt = 0; kt < nkt; kt++) {
        if (kt + 1 < nkt) { load_tiles((kt + 1) & 1, kt + 1); CP_COMMIT(); CP_WAIT(1); }
        else              { CP_WAIT(0); }
        __syncthreads();

        const int st = kt & 1;

        // ---- S = Q K^T (single-term f16) ----
        float s[8][4];
        #pragma unroll
        for (int j = 0; j < 8; j++) { s[j][0] = s[j][1] = s[j][2] = s[j][3] = 0.f; }

        #pragma unroll
        for (int j = 0; j < 8; j++) {
            uint32_t kf[4];
            const uint32_t off = (uint32_t)((j * 8 + lm_row) * KSTR + lm_cb * 8) * 2;
            ldm4(kf, aK[st] + off);
            mma16816(s[j], qh[0], kf[0], kf[1]);
            mma16816(s[j], qh[1], kf[2], kf[3]);
        }

        // ---- p = 2^s, diagonal mask, row sums ----
        const bool diag = (qt >= 16) && (kt == qt);
        #pragma unroll
        for (int j = 0; j < 8; j++) {
            float p0 = ex2(s[j][0]), p1 = ex2(s[j][1]);
            float p2 = ex2(s[j][2]), p3 = ex2(s[j][3]);
            if (diag) {
                const int key0 = kt * 64 + j * 8 + t4 * 2;
                const int r0 = qt * 64 + wid * 16 + r4;
                if (key0     > r0)     p0 = 0.f;
                if (key0 + 1 > r0)     p1 = 0.f;
                if (key0     > r0 + 8) p2 = 0.f;
                if (key0 + 1 > r0 + 8) p3 = 0.f;
            }
            l0 += p0 + p1; l1 += p2 + p3;
            s[j][0] = p0; s[j][1] = p1; s[j][2] = p2; s[j][3] = p3;
        }

        // ---- P -> f16 A frags ----
        uint32_t ah[4][4];
        #pragma unroll
        for (int kk = 0; kk < 4; kk++) {
            const int j0 = 2 * kk, j1 = 2 * kk + 1;
            ah[kk][0] = pack_f16(s[j0][0], s[j0][1]);
            ah[kk][1] = pack_f16(s[j0][2], s[j0][3]);
            ah[kk][2] = pack_f16(s[j1][0], s[j1][1]);
            ah[kk][3] = pack_f16(s[j1][2], s[j1][3]);
        }

        // ---- O += P V ----
        #pragma unroll
        for (int nd = 0; nd < 4; nd++) {
            uint32_t vh[8];
            const uint32_t ro = (uint32_t)((nd * 8 + lm_row) * VSTR) * 2;
            ldm4(vh,     aVh[st] + ro + (uint32_t)(lm_cb * 8) * 2);
            ldm4(vh + 4, aVh[st] + ro + (uint32_t)(32 + lm_cb * 8) * 2);
            #pragma unroll
            for (int kk = 0; kk < 4; kk++)
                mma16816(o[nd], ah[kk], vh[2 * kk], vh[2 * kk + 1]);
        }
        __syncthreads();
    }

    l0 += __shfl_xor_sync(0xffffffffu, l0, 1);
    l0 += __shfl_xor_sync(0xffffffffu, l0, 2);
    l1 += __shfl_xor_sync(0xffffffffu, l1, 1);
    l1 += __shfl_xor_sync(0xffffffffu, l1, 2);
    const float inv0 = 1.f / l0, inv1 = 1.f / l1;

    const int row0 = qt * 64 + wid * 16 + r4;
    #pragma unroll
    for (int nd = 0; nd < 4; nd++) {
        const int d0 = nd * 8 + t4 * 2;
        const size_t o0 = ((size_t)(b * SEQ + row0)) * DIM + h * HD + d0;
        const size_t o1 = ((size_t)(b * SEQ + row0 + 8)) * DIM + h * HD + d0;
        *reinterpret_cast<float2*>(&out[o0]) = make_float2(o[nd][0] * inv0, o[nd][1] * inv0);
        *reinterpret_cast<float2*>(&out[o1]) = make_float2(o[nd][2] * inv1, o[nd][3] * inv1);
    }
}

extern "C" void kernel_launch(void* const* d_in, const int* in_sizes, int n_in,
                              void* d_out, int out_size) {
    const float* x    = (const float*)d_in[0];
    const float* W    = (const float*)d_in[1];
    const float* bias = (const float*)d_in[2];
    float* out = (float*)d_out;

    static int init_done = 0;
    if (!init_done) {
        cudaFuncSetAttribute(qkv_mma,
                             cudaFuncAttributeMaxDynamicSharedMemorySize,
                             8 * TILEB * (int)sizeof(__half));
        init_done = 1;
    }

    xsplit<<<2048, 256>>>(x);
    wsplit<<<dim3(12, 4), 256>>>(W);
    qkv_mma<<<dim3(64, 6), 256, 8 * TILEB * sizeof(__half)>>>(bias);

    dim3 vt_grid(16, 32);
    vtrans<<<vt_grid, 256>>>();

    dim3 attn_grid(32, 32);
    flash_attn<<<attn_grid, 128>>>(out);
}

// round 13
// speedup vs baseline: 1.5789x; 1.1499x over previous
#include <cuda_runtime.h>
#include <cuda_fp16.h>
#include <cstdint>

#define SEQ     2048
#define DIM     256
#define NHEAD   8
#define HD      32
#define NBATCH  4
#define NBH     (NBATCH * NHEAD)
#define QK_SCALE_L2E (0.17677669529663687f * 1.4426950408889634f)  // 32^-0.5 * log2(e)

// f16 attention operands
__device__ __align__(16) __half g_q16[NBH * SEQ * HD];   // Q f16 (pre-scaled), [bh][n][d]
__device__ __align__(16) __half g_k16[NBH * SEQ * HD];   // K f16, [bh][n][d]
__device__ __align__(16) __half g_vth[NBH * HD * SEQ];   // V^T f16, [bh][d][n]
// GEMM operands: x rounded to f16; W split hi/lo (keeps GEMM 2-term accurate)
__device__ __align__(16) __half g_xh[8192 * 256];        // x f16, [m][k]
__device__ __align__(16) __half g_wh[768 * 256];         // W^T hi, [n][k]
__device__ __align__(16) __half g_wl[768 * 256];         // W^T lo

// ---------------------------------------------------------------------------
// helpers
// ---------------------------------------------------------------------------
__device__ __forceinline__ uint32_t pack_f16(float x0, float x1) {
    __half2 hh = __floats2half2_rn(x0, x1);
    return *reinterpret_cast<uint32_t*>(&hh);
}
__device__ __forceinline__ void split_pack_f16(float x0, float x1,
                                               uint32_t& h, uint32_t& l) {
    __half2 hh = __floats2half2_rn(x0, x1);
    float2 hf = __half22float2(hh);
    __half2 ll = __floats2half2_rn(x0 - hf.x, x1 - hf.y);
    h = *reinterpret_cast<uint32_t*>(&hh);
    l = *reinterpret_cast<uint32_t*>(&ll);
}
__device__ __forceinline__ float ex2(float x) {
    float y;
    asm("ex2.approx.f32 %0, %1;" : "=f"(y) : "f"(x));
    return y;
}

__device__ __forceinline__ void mma16816(float* c, const uint32_t* a,
                                         uint32_t b0, uint32_t b1) {
    asm volatile(
        "mma.sync.aligned.m16n8k16.row.col.f32.f16.f16.f32 "
        "{%0,%1,%2,%3}, {%4,%5,%6,%7}, {%8,%9}, {%0,%1,%2,%3};"
        : "+f"(c[0]), "+f"(c[1]), "+f"(c[2]), "+f"(c[3])
        : "r"(a[0]), "r"(a[1]), "r"(a[2]), "r"(a[3]), "r"(b0), "r"(b1));
}

__device__ __forceinline__ void ldm4(uint32_t* r, uint32_t saddr) {
    asm volatile("ldmatrix.sync.aligned.m8n8.x4.shared.b16 {%0,%1,%2,%3}, [%4];"
                 : "=r"(r[0]), "=r"(r[1]), "=r"(r[2]), "=r"(r[3]) : "r"(saddr));
}

__device__ __forceinline__ void cpa16(uint32_t s, const void* g) {
    uint64_t ga;
    asm("cvta.to.global.u64 %0, %1;" : "=l"(ga) : "l"(g));
    asm volatile("cp.async.cg.shared.global [%0], [%1], 16;" :: "r"(s), "l"(ga));
}
#define CP_COMMIT() asm volatile("cp.async.commit_group;" ::: "memory")
#define CP_WAIT(n)  asm volatile("cp.async.wait_group %0;" :: "n"(n) : "memory")

__device__ __forceinline__ uint32_t smem_u32(const void* p) {
    return (uint32_t)__cvta_generic_to_shared(p);
}

// ---------------------------------------------------------------------------
// Prep A: round x -> f16
// ---------------------------------------------------------------------------
__global__ __launch_bounds__(256) void xsplit(const float* __restrict__ x) {
    const size_t e0 = ((size_t)blockIdx.x * 256 + threadIdx.x) * 4;
    float4 v = *reinterpret_cast<const float4*>(&x[e0]);
    *reinterpret_cast<uint2*>(&g_xh[e0]) =
        make_uint2(pack_f16(v.x, v.y), pack_f16(v.z, v.w));
}

// ---------------------------------------------------------------------------
// Prep B: transpose + split W [k=256][n=768] -> W^T hi/lo [n][k]
// ---------------------------------------------------------------------------
__global__ __launch_bounds__(256) void wsplit(const float* __restrict__ W) {
    __shared__ float Ws[64][65];
    const int tid = threadIdx.x;
    const int n0 = blockIdx.x * 64;
    const int k0 = blockIdx.y * 64;

    const int kr = tid >> 2, nc = (tid & 3) << 4;
    #pragma unroll
    for (int j = 0; j < 4; j++) {
        float4 v = *reinterpret_cast<const float4*>(&W[(size_t)(k0 + kr) * 768 + n0 + nc + j * 4]);
        Ws[kr][nc + j * 4 + 0] = v.x; Ws[kr][nc + j * 4 + 1] = v.y;
        Ws[kr][nc + j * 4 + 2] = v.z; Ws[kr][nc + j * 4 + 3] = v.w;
    }
    __syncthreads();

    const int nr = tid >> 2, ks = (tid & 3) << 4;
    uint32_t hw[8], lw[8];
    #pragma unroll
    for (int j = 0; j < 8; j++)
        split_pack_f16(Ws[ks + 2 * j][nr], Ws[ks + 2 * j + 1][nr], hw[j], lw[j]);
    const size_t ob = (size_t)(n0 + nr) * 256 + k0 + ks;
    *reinterpret_cast<uint4*>(&g_wh[ob])     = make_uint4(hw[0], hw[1], hw[2], hw[3]);
    *reinterpret_cast<uint4*>(&g_wh[ob + 8]) = make_uint4(hw[4], hw[5], hw[6], hw[7]);
    *reinterpret_cast<uint4*>(&g_wl[ob])     = make_uint4(lw[0], lw[1], lw[2], lw[3]);
    *reinterpret_cast<uint4*>(&g_wl[ob + 8]) = make_uint4(lw[4], lw[5], lw[6], lw[7]);
}

// ---------------------------------------------------------------------------
// QKV GEMM via mma.sync f16, 2-term (x_f16 * (Wh + Wl)).
// CTA 128x128, 8 warps (2m x 4n), k-chunk 32, cp.async double buffer.
// V CTAs transpose in-smem and write g_vth directly (vtrans fused).
// ---------------------------------------------------------------------------
#define ASTR 40
#define TILEB (128 * ASTR)   // f16 elems per buffer

__global__ __launch_bounds__(256) void qkv_mma(const float* __restrict__ bias) {
    extern __shared__ __half sm[];
    __half* sA [2] = { sm,             sm + 3 * TILEB };
    __half* sBh[2] = { sm + 1 * TILEB, sm + 4 * TILEB };
    __half* sBl[2] = { sm + 2 * TILEB, sm + 5 * TILEB };

    const int tid  = threadIdx.x;
    const int lane = tid & 31;
    const int wid  = tid >> 5;
    const int wm = wid & 1, wn = wid >> 1;
    const int m0 = blockIdx.x * 128;
    const int n0 = blockIdx.y * 128;

    const int crow = tid >> 1, cseg = (tid & 1) << 4;
    const uint32_t soff = (uint32_t)(crow * ASTR + cseg) * 2;

    auto load_stage = [&](int st, int kc) {
        const size_t ga = (size_t)(m0 + crow) * 256 + kc * 32 + cseg;
        const size_t gb = (size_t)(n0 + crow) * 256 + kc * 32 + cseg;
        uint32_t aa = smem_u32(sA[st])  + soff;
        uint32_t bh = smem_u32(sBh[st]) + soff;
        uint32_t bl = smem_u32(sBl[st]) + soff;
        cpa16(aa, g_xh + ga); cpa16(aa + 16, g_xh + ga + 8);
        cpa16(bh, g_wh + gb); cpa16(bh + 16, g_wh + gb + 8);
        cpa16(bl, g_wl + gb); cpa16(bl + 16, g_wl + gb + 8);
    };

    float c[4][4][4];
    #pragma unroll
    for (int mi = 0; mi < 4; mi++)
        #pragma unroll
        for (int j = 0; j < 4; j++)
            { c[mi][j][0] = c[mi][j][1] = c[mi][j][2] = c[mi][j][3] = 0.f; }

    const int a_r = (lane & 7) + ((lane >> 3) & 1) * 8;
    const int a_c = (lane >> 4) * 8;
    const int b_r = lane & 7;
    const int b_c = (lane >> 3) * 8;

    load_stage(0, 0);
    CP_COMMIT();

    for (int kc = 0; kc < 8; kc++) {
        if (kc + 1 < 8) { load_stage((kc + 1) & 1, kc + 1); CP_COMMIT(); CP_WAIT(1); }
        else            { CP_WAIT(0); }
        __syncthreads();
        const int st = kc & 1;

        uint32_t bh[4][4], bl[4][4];
        const uint32_t bbase_h = smem_u32(sBh[st]);
        const uint32_t bbase_l = smem_u32(sBl[st]);
        #pragma unroll
        for (int j = 0; j < 4; j++) {
            const uint32_t off = (uint32_t)((wn * 32 + j * 8 + b_r) * ASTR + b_c) * 2;
            ldm4(bh[j], bbase_h + off);
            ldm4(bl[j], bbase_l + off);
        }

        const uint32_t abase = smem_u32(sA[st]);
        #pragma unroll
        for (int mi = 0; mi < 4; mi++) {
            uint32_t ah[2][4];
            #pragma unroll
            for (int kk = 0; kk < 2; kk++) {
                const uint32_t off =
                    (uint32_t)((wm * 64 + mi * 16 + a_r) * ASTR + kk * 16 + a_c) * 2;
                ldm4(ah[kk], abase + off);
            }
            #pragma unroll
            for (int j = 0; j < 4; j++) {
                mma16816(c[mi][j], ah[0], bh[j][0], bh[j][1]);
                mma16816(c[mi][j], ah[1], bh[j][2], bh[j][3]);
                mma16816(c[mi][j], ah[0], bl[j][0], bl[j][1]);
                mma16816(c[mi][j], ah[1], bl[j][2], bl[j][3]);
            }
        }
        __syncthreads();
    }

    // ---- epilogue ----
    const int which = n0 >> 8;            // 0=Q 1=K 2=V
    const int r4 = lane >> 2, t4 = lane & 3;

    if (which == 2) {
        // stage V f16 into smem [128 m][65-padded u32 cols], then write g_vth
        uint32_t* Vu = reinterpret_cast<uint32_t*>(sm);
        #pragma unroll
        for (int j = 0; j < 4; j++) {
            const int n3 = n0 + wn * 32 + j * 8 + t4 * 2;
            const float b0 = __ldg(&bias[n3]), b1 = __ldg(&bias[n3 + 1]);
            const int colh = (wn * 32 + j * 8 + t4 * 2) >> 1;   // u32 col 0..63
            #pragma unroll
            for (int mi = 0; mi < 4; mi++)
                #pragma unroll
                for (int half = 0; half < 2; half++) {
                    const int ml = wm * 64 + mi * 16 + r4 + half * 8;
                    Vu[ml * 65 + colh] =
                        pack_f16(c[mi][j][2 * half + 0] + b0,
                                 c[mi][j][2 * half + 1] + b1);
                }
        }
        __syncthreads();

        const int col = tid & 127;        // local col = head_local*32 + d
        const int nh  = tid >> 7;         // 0/1: n half
        const int bb  = m0 >> 11;
        const int nb  = m0 & 2047;
        const int head = ((n0 == 640) ? 4 : 0) + (col >> 5);
        const int d    = col & 31;
        const int ch   = col >> 1;
        const uint32_t sel = (col & 1) ? 0x7632u : 0x5410u;
        uint32_t* gt = reinterpret_cast<uint32_t*>(g_vth);
        const size_t obase =
            ((((size_t)(bb * NHEAD + head)) * HD + d) * SEQ + nb + nh * 64) >> 1;
        #pragma unroll
        for (int g4 = 0; g4 < 8; g4++) {
            uint32_t w[4];
            #pragma unroll
            for (int q = 0; q < 4; q++) {
                const int n2 = nh * 64 + g4 * 8 + q * 2;
                w[q] = __byte_perm(Vu[n2 * 65 + ch], Vu[(n2 + 1) * 65 + ch], sel);
            }
            *reinterpret_cast<uint4*>(gt + obase + g4 * 4) =
                make_uint4(w[0], w[1], w[2], w[3]);
        }
    } else {
        #pragma unroll
        for (int j = 0; j < 4; j++) {
            const int n3 = n0 + wn * 32 + j * 8 + t4 * 2;
            const int cc = n3 & 255, h = cc >> 5, d = cc & 31;
            const float b0 = __ldg(&bias[n3]), b1 = __ldg(&bias[n3 + 1]);
            #pragma unroll
            for (int mi = 0; mi < 4; mi++)
                #pragma unroll
                for (int half = 0; half < 2; half++) {
                    const int m = m0 + wm * 64 + mi * 16 + r4 + half * 8;
                    const int bb = m >> 11, n = m & 2047;
                    float v0 = c[mi][j][2 * half + 0] + b0;
                    float v1 = c[mi][j][2 * half + 1] + b1;
                    const size_t idx = ((size_t)(bb * NHEAD + h) * SEQ + n) * HD + d;
                    if (which == 0) {
                        *reinterpret_cast<uint32_t*>(&g_q16[idx]) =
                            pack_f16(v0 * QK_SCALE_L2E, v1 * QK_SCALE_L2E);
                    } else {
                        *reinterpret_cast<uint32_t*>(&g_k16[idx]) = pack_f16(v0, v1);
                    }
                }
        }
    }
}

// ---------------------------------------------------------------------------
// Flash attention (R12 winner, unchanged): 64-row q-tile, 4 warps, 1024 CTAs,
// QK single-term f16, PV single-term, exp2 softmax (log2e folded into Q).
// ---------------------------------------------------------------------------
#define KSTR 40
#define VSTR 72

__global__ __launch_bounds__(128) void flash_attn(float* __restrict__ out) {
    __shared__ __half sK [2][64 * KSTR];
    __shared__ __half sVh[2][32 * VSTR];

    const int tid  = threadIdx.x;
    const int lane = tid & 31;
    const int wid  = tid >> 5;
    const int qt   = 31 - blockIdx.x;     // heavy (long causal) tiles first
    const int bh   = blockIdx.y;
    const int b    = bh >> 3, h = bh & 7;

    const uint32_t aK [2] = { smem_u32(sK[0]),  smem_u32(sK[1])  };
    const uint32_t aVh[2] = { smem_u32(sVh[0]), smem_u32(sVh[1]) };

    uint32_t qh[2][4];
    {
        const size_t qbase = ((size_t)bh * SEQ + qt * 64 + wid * 16) * HD;
        const uint32_t* qhp = reinterpret_cast<const uint32_t*>(g_q16) + qbase / 2;
        const int r = lane >> 2, t4 = lane & 3;
        #pragma unroll
        for (int kk = 0; kk < 2; kk++) {
            qh[kk][0] = qhp[r * 16 + kk * 8 + t4];
            qh[kk][1] = qhp[(r + 8) * 16 + kk * 8 + t4];
            qh[kk][2] = qhp[r * 16 + kk * 8 + 4 + t4];
            qh[kk][3] = qhp[(r + 8) * 16 + kk * 8 + 4 + t4];
        }
    }

    const int nkt = (qt < 16) ? 16 : (qt + 1);
    float o[4][4] = {};
    float l0 = 0.f, l1 = 0.f;

    auto load_tiles = [&](int st, int kt) {
        {
            const int row = tid >> 1, seg = (tid & 1) << 4;
            const size_t gk = ((size_t)bh * SEQ + kt * 64 + row) * HD + seg;
            const uint32_t sk = (uint32_t)(row * KSTR + seg) * 2;
            cpa16(aK[st] + sk,      g_k16 + gk);
            cpa16(aK[st] + sk + 16, g_k16 + gk + 8);
        }
        {
            const int dr = tid >> 2, seg = (tid & 3) << 4;
            const size_t gv = ((size_t)bh * HD + dr) * SEQ + kt * 64 + seg;
            const uint32_t sv = (uint32_t)(dr * VSTR + seg) * 2;
            cpa16(aVh[st] + sv,      g_vth + gv);
            cpa16(aVh[st] + sv + 16, g_vth + gv + 8);
        }
    };

    load_tiles(0, 0);
    CP_COMMIT();

    const int r4 = lane >> 2, t4 = lane & 3;
    const int lm_row = lane & 7, lm_cb = lane >> 3;

    for (int kt = 0; kt < nkt; kt++) {
        if (kt + 1 < nkt) { load_tiles((kt + 1) & 1, kt + 1); CP_COMMIT(); CP_WAIT(1); }
        else              { CP_WAIT(0); }
        __syncthreads();

        const int st = kt & 1;

        float s[8][4];
        #pragma unroll
        for (int j = 0; j < 8; j++) { s[j][0] = s[j][1] = s[j][2] = s[j][3] = 0.f; }

        #pragma unroll
        for (int j = 0; j < 8; j++) {
            uint32_t kf[4];
            const uint32_t off = (uint32_t)((j * 8 + lm_row) * KSTR + lm_cb * 8) * 2;
            ldm4(kf, aK[st] + off);
            mma16816(s[j], qh[0], kf[0], kf[1]);
            mma16816(s[j], qh[1], kf[2], kf[3]);
        }

        const bool diag = (qt >= 16) && (kt == qt);
        #pragma unroll
        for (int j = 0; j < 8; j++) {
            float p0 = ex2(s[j][0]), p1 = ex2(s[j][1]);
            float p2 = ex2(s[j][2]), p3 = ex2(s[j][3]);
            if (diag) {
                const int key0 = kt * 64 + j * 8 + t4 * 2;
                const int r0 = qt * 64 + wid * 16 + r4;
                if (key0     > r0)     p0 = 0.f;
                if (key0 + 1 > r0)     p1 = 0.f;
                if (key0     > r0 + 8) p2 = 0.f;
                if (key0 + 1 > r0 + 8) p3 = 0.f;
            }
            l0 += p0 + p1; l1 += p2 + p3;
            s[j][0] = p0; s[j][1] = p1; s[j][2] = p2; s[j][3] = p3;
        }

        uint32_t ah[4][4];
        #pragma unroll
        for (int kk = 0; kk < 4; kk++) {
            const int j0 = 2 * kk, j1 = 2 * kk + 1;
            ah[kk][0] = pack_f16(s[j0][0], s[j0][1]);
            ah[kk][1] = pack_f16(s[j0][2], s[j0][3]);
            ah[kk][2] = pack_f16(s[j1][0], s[j1][1]);
            ah[kk][3] = pack_f16(s[j1][2], s[j1][3]);
        }

        #pragma unroll
        for (int nd = 0; nd < 4; nd++) {
            uint32_t vh[8];
            const uint32_t ro = (uint32_t)((nd * 8 + lm_row) * VSTR) * 2;
            ldm4(vh,     aVh[st] + ro + (uint32_t)(lm_cb * 8) * 2);
            ldm4(vh + 4, aVh[st] + ro + (uint32_t)(32 + lm_cb * 8) * 2);
            #pragma unroll
            for (int kk = 0; kk < 4; kk++)
                mma16816(o[nd], ah[kk], vh[2 * kk], vh[2 * kk + 1]);
        }
        __syncthreads();
    }

    l0 += __shfl_xor_sync(0xffffffffu, l0, 1);
    l0 += __shfl_xor_sync(0xffffffffu, l0, 2);
    l1 += __shfl_xor_sync(0xffffffffu, l1, 1);
    l1 += __shfl_xor_sync(0xffffffffu, l1, 2);
    const float inv0 = 1.f / l0, inv1 = 1.f / l1;

    const int row0 = qt * 64 + wid * 16 + r4;
    #pragma unroll
    for (int nd = 0; nd < 4; nd++) {
        const int d0 = nd * 8 + t4 * 2;
        const size_t o0 = ((size_t)(b * SEQ + row0)) * DIM + h * HD + d0;
        const size_t o1 = ((size_t)(b * SEQ + row0 + 8)) * DIM + h * HD + d0;
        *reinterpret_cast<float2*>(&out[o0]) = make_float2(o[nd][0] * inv0, o[nd][1] * inv0);
        *reinterpret_cast<float2*>(&out[o1]) = make_float2(o[nd][2] * inv1, o[nd][3] * inv1);
    }
}

extern "C" void kernel_launch(void* const* d_in, const int* in_sizes, int n_in,
                              void* d_out, int out_size) {
    const float* x    = (const float*)d_in[0];
    const float* W    = (const float*)d_in[1];
    const float* bias = (const float*)d_in[2];
    float* out = (float*)d_out;

    static int init_done = 0;
    if (!init_done) {
        cudaFuncSetAttribute(qkv_mma,
                             cudaFuncAttributeMaxDynamicSharedMemorySize,
                             6 * TILEB * (int)sizeof(__half));
        init_done = 1;
    }

    xsplit<<<2048, 256>>>(x);
    wsplit<<<dim3(12, 4), 256>>>(W);
    qkv_mma<<<dim3(64, 6), 256, 6 * TILEB * sizeof(__half)>>>(bias);

    dim3 attn_grid(32, 32);
    flash_attn<<<attn_grid, 128>>>(out);
}